// round 6
// baseline (speedup 1.0000x reference)
#include <cuda_runtime.h>
#include <cuda_bf16.h>
#include <math.h>
#include <stdint.h>

#define Tn 2048
#define Dn 1024
#define Hn 4096
#define Ln 8
#define Vn 50257
#define VP 50304
#define EPSn 1e-5f

// ---------------- weight pool offsets (elements) ----------------
#define OFF_TWK  0u
#define OFF_TWV  8388608u
#define OFF_TWR  16777216u
#define OFF_TWO  25165824u
#define OFF_CWK  33554432u
#define OFF_CWV  67108864u
#define OFF_CWR  100663296u
#define OFF_HEAD 109051904u
#define WTOTAL   160563200u

// ---------------- scratch (no allocations allowed) ----------------
__device__ float g_x [Tn*Dn];
__device__ float g_xn[Tn*Dn];
__device__ float g_k [Tn*Dn];
__device__ float g_v [Tn*Dn];
__device__ float g_r [Tn*Dn];
__device__ float g_rr[Tn*Dn];

__device__ __nv_bfloat16 g_wh[WTOTAL];
__device__ __nv_bfloat16 g_wl[WTOTAL];

__device__ __nv_bfloat16 g_xkh[Tn*Dn], g_xkl[Tn*Dn];
__device__ __nv_bfloat16 g_xvh[Tn*Dn], g_xvl[Tn*Dn];
__device__ __nv_bfloat16 g_xrh[Tn*Dn], g_xrl[Tn*Dn];
__device__ __nv_bfloat16 g_ryh[Tn*Dn], g_ryl[Tn*Dn];
__device__ __nv_bfloat16 g_xnh[Tn*Dn], g_xnl[Tn*Dn];
__device__ __nv_bfloat16 g_kkh[Tn*Hn], g_kkl[Tn*Hn];

// ---------------- PTX helpers (portable PTX only) ----------------
__device__ __forceinline__ uint32_t smem_u32(const void* p) {
    uint32_t a;
    asm("{ .reg .u64 t; cvta.to.shared.u64 t, %1; cvt.u32.u64 %0, t; }" : "=r"(a) : "l"(p));
    return a;
}

#define LDSM_X4(addr, r0, r1, r2, r3) \
    asm volatile("ldmatrix.sync.aligned.m8n8.x4.shared.b16 {%0,%1,%2,%3}, [%4];" \
        : "=r"(r0), "=r"(r1), "=r"(r2), "=r"(r3) : "r"(addr))

#define LDSM_X4T(addr, r0, r1, r2, r3) \
    asm volatile("ldmatrix.sync.aligned.m8n8.x4.trans.shared.b16 {%0,%1,%2,%3}, [%4];" \
        : "=r"(r0), "=r"(r1), "=r"(r2), "=r"(r3) : "r"(addr))

__device__ __forceinline__ void mma_bf16(float* c, const uint32_t* a,
                                         uint32_t b0, uint32_t b1) {
    asm volatile(
        "mma.sync.aligned.m16n8k16.row.col.f32.bf16.bf16.f32 "
        "{%0,%1,%2,%3}, {%4,%5,%6,%7}, {%8,%9}, {%0,%1,%2,%3};"
        : "+f"(c[0]), "+f"(c[1]), "+f"(c[2]), "+f"(c[3])
        : "r"(a[0]), "r"(a[1]), "r"(a[2]), "r"(a[3]), "r"(b0), "r"(b1));
}

__device__ __forceinline__ void cpa16(uint32_t dst, const void* src) {
    asm volatile("cp.async.cg.shared.global [%0], [%1], 16;"
                 :: "r"(dst), "l"(src) : "memory");
}
#define CP_COMMIT() asm volatile("cp.async.commit_group;" ::: "memory")
#define CP_WAIT1()  asm volatile("cp.async.wait_group 1;" ::: "memory")

// split (x,y) into bf16 hi/lo pairs packed as bf16x2 words
__device__ __forceinline__ void split2(float x, float y, uint32_t& h, uint32_t& l) {
    __nv_bfloat16 hx = __float2bfloat16_rn(x);
    __nv_bfloat16 hy = __float2bfloat16_rn(y);
    float rx = x - __bfloat162float(hx);
    float ry = y - __bfloat162float(hy);
    __nv_bfloat162 hp; hp.x = hx; hp.y = hy;
    __nv_bfloat162 lp; lp.x = __float2bfloat16_rn(rx); lp.y = __float2bfloat16_rn(ry);
    h = *reinterpret_cast<uint32_t*>(&hp);
    l = *reinterpret_cast<uint32_t*>(&lp);
}

// ---------------- weight split ([rows, srccols] -> padded [rows, dstcols]) ----
__global__ void __launch_bounds__(256)
wsplit_kernel(const float* __restrict__ src, __nv_bfloat16* __restrict__ dh,
              __nv_bfloat16* __restrict__ dl, int srccols, int dstcols)
{
    int r = blockIdx.y;
    const float* s = src + (size_t)r * srccols;
    uint32_t* ph = reinterpret_cast<uint32_t*>(dh + (size_t)r * dstcols);
    uint32_t* pl = reinterpret_cast<uint32_t*>(dl + (size_t)r * dstcols);
    for (int c0 = (blockIdx.x * 256 + threadIdx.x) * 2; c0 < dstcols;
         c0 += gridDim.x * 256 * 2) {
        float v0 = (c0     < srccols) ? s[c0]     : 0.f;
        float v1 = (c0 + 1 < srccols) ? s[c0 + 1] : 0.f;
        uint32_t h, l;
        split2(v0, v1, h, l);
        ph[c0 >> 1] = h;
        pl[c0 >> 1] = l;
    }
}

// ---------------- LayerNorm (fp32 out; optional embedding gather) ------------
__global__ void __launch_bounds__(256)
ln_kernel(const float* __restrict__ x, const int* __restrict__ tokens,
          const float* __restrict__ w, const float* __restrict__ b,
          float* __restrict__ y)
{
    __shared__ float sh0[8], sh1[8];
    int t = blockIdx.x;
    const float* row;
    if (tokens) row = x + (size_t)tokens[t] * Dn;
    else        row = x + (size_t)t * Dn;

    float4 vv = reinterpret_cast<const float4*>(row)[threadIdx.x];
    float s  = vv.x + vv.y + vv.z + vv.w;
    float s2 = vv.x*vv.x + vv.y*vv.y + vv.z*vv.z + vv.w*vv.w;
    #pragma unroll
    for (int o = 16; o > 0; o >>= 1) {
        s  += __shfl_down_sync(0xffffffffu, s,  o);
        s2 += __shfl_down_sync(0xffffffffu, s2, o);
    }
    int wid = threadIdx.x >> 5, lid = threadIdx.x & 31;
    if (lid == 0) { sh0[wid] = s; sh1[wid] = s2; }
    __syncthreads();
    if (threadIdx.x < 32) {
        s  = (lid < 8) ? sh0[lid] : 0.f;
        s2 = (lid < 8) ? sh1[lid] : 0.f;
        #pragma unroll
        for (int o = 4; o > 0; o >>= 1) {
            s  += __shfl_down_sync(0xffffffffu, s,  o);
            s2 += __shfl_down_sync(0xffffffffu, s2, o);
        }
        if (lid == 0) { sh0[0] = s; sh1[0] = s2; }
    }
    __syncthreads();
    float mu  = sh0[0] * (1.f / Dn);
    float var = sh1[0] * (1.f / Dn) - mu * mu;
    float rstd = rsqrtf(var + EPSn);

    float4 wv = reinterpret_cast<const float4*>(w)[threadIdx.x];
    float4 bv = reinterpret_cast<const float4*>(b)[threadIdx.x];
    float4 o4;
    o4.x = (vv.x - mu) * rstd * wv.x + bv.x;
    o4.y = (vv.y - mu) * rstd * wv.y + bv.y;
    o4.z = (vv.z - mu) * rstd * wv.z + bv.z;
    o4.w = (vv.w - mu) * rstd * wv.w + bv.w;
    reinterpret_cast<float4*>(y + (size_t)t * Dn)[threadIdx.x] = o4;
}

// ---------------- LayerNorm with bf16 hi/lo split output ---------------------
__global__ void __launch_bounds__(256)
ln_split_kernel(const float* __restrict__ x,
                const float* __restrict__ w, const float* __restrict__ b,
                __nv_bfloat16* __restrict__ yh, __nv_bfloat16* __restrict__ yl)
{
    __shared__ float sh0[8], sh1[8];
    int t = blockIdx.x;
    const float* row = x + (size_t)t * Dn;

    float4 vv = reinterpret_cast<const float4*>(row)[threadIdx.x];
    float s  = vv.x + vv.y + vv.z + vv.w;
    float s2 = vv.x*vv.x + vv.y*vv.y + vv.z*vv.z + vv.w*vv.w;
    #pragma unroll
    for (int o = 16; o > 0; o >>= 1) {
        s  += __shfl_down_sync(0xffffffffu, s,  o);
        s2 += __shfl_down_sync(0xffffffffu, s2, o);
    }
    int wid = threadIdx.x >> 5, lid = threadIdx.x & 31;
    if (lid == 0) { sh0[wid] = s; sh1[wid] = s2; }
    __syncthreads();
    if (threadIdx.x < 32) {
        s  = (lid < 8) ? sh0[lid] : 0.f;
        s2 = (lid < 8) ? sh1[lid] : 0.f;
        #pragma unroll
        for (int o = 4; o > 0; o >>= 1) {
            s  += __shfl_down_sync(0xffffffffu, s,  o);
            s2 += __shfl_down_sync(0xffffffffu, s2, o);
        }
        if (lid == 0) { sh0[0] = s; sh1[0] = s2; }
    }
    __syncthreads();
    float mu  = sh0[0] * (1.f / Dn);
    float var = sh1[0] * (1.f / Dn) - mu * mu;
    float rstd = rsqrtf(var + EPSn);

    float4 wv = reinterpret_cast<const float4*>(w)[threadIdx.x];
    float4 bv = reinterpret_cast<const float4*>(b)[threadIdx.x];
    float o0 = (vv.x - mu) * rstd * wv.x + bv.x;
    float o1 = (vv.y - mu) * rstd * wv.y + bv.y;
    float o2 = (vv.z - mu) * rstd * wv.z + bv.z;
    float o3 = (vv.w - mu) * rstd * wv.w + bv.w;
    uint32_t h0, l0, h1, l1;
    split2(o0, o1, h0, l0);
    split2(o2, o3, h1, l1);
    uint32_t base = (uint32_t)(((size_t)t * Dn) >> 1) + threadIdx.x * 2;
    reinterpret_cast<uint32_t*>(yh)[base]     = h0;
    reinterpret_cast<uint32_t*>(yh)[base + 1] = h1;
    reinterpret_cast<uint32_t*>(yl)[base]     = l0;
    reinterpret_cast<uint32_t*>(yl)[base + 1] = l1;
}

// ---------------- time-shift mixes, writing bf16 hi/lo directly --------------
__global__ void __launch_bounds__(256)
mix3_split_kernel(const float* __restrict__ x,
                  const float* __restrict__ mk, const float* __restrict__ mv,
                  const float* __restrict__ mr)
{
    int idx = blockIdx.x * 256 + threadIdx.x;          // pair index
    if (idx >= Tn * Dn / 2) return;
    int i0 = idx * 2;
    int d0 = i0 & (Dn - 1);
    float2 c = *reinterpret_cast<const float2*>(x + i0);
    float2 p = make_float2(0.f, 0.f);
    if (i0 >= Dn) p = *reinterpret_cast<const float2*>(x + i0 - Dn);

    uint32_t h, l;
    float a0, a1, v0, v1;

    a0 = mk[d0]; a1 = mk[d0 + 1];
    v0 = c.x * a0 + p.x * (1.f - a0);
    v1 = c.y * a1 + p.y * (1.f - a1);
    split2(v0, v1, h, l);
    reinterpret_cast<uint32_t*>(g_xkh)[idx] = h;
    reinterpret_cast<uint32_t*>(g_xkl)[idx] = l;

    a0 = mv[d0]; a1 = mv[d0 + 1];
    v0 = c.x * a0 + p.x * (1.f - a0);
    v1 = c.y * a1 + p.y * (1.f - a1);
    split2(v0, v1, h, l);
    reinterpret_cast<uint32_t*>(g_xvh)[idx] = h;
    reinterpret_cast<uint32_t*>(g_xvl)[idx] = l;

    a0 = mr[d0]; a1 = mr[d0 + 1];
    v0 = c.x * a0 + p.x * (1.f - a0);
    v1 = c.y * a1 + p.y * (1.f - a1);
    split2(v0, v1, h, l);
    reinterpret_cast<uint32_t*>(g_xrh)[idx] = h;
    reinterpret_cast<uint32_t*>(g_xrl)[idx] = l;
}

__global__ void __launch_bounds__(256)
mix2_split_kernel(const float* __restrict__ x,
                  const float* __restrict__ mk, const float* __restrict__ mr)
{
    int idx = blockIdx.x * 256 + threadIdx.x;
    if (idx >= Tn * Dn / 2) return;
    int i0 = idx * 2;
    int d0 = i0 & (Dn - 1);
    float2 c = *reinterpret_cast<const float2*>(x + i0);
    float2 p = make_float2(0.f, 0.f);
    if (i0 >= Dn) p = *reinterpret_cast<const float2*>(x + i0 - Dn);

    uint32_t h, l;
    float a0, a1, v0, v1;

    a0 = mk[d0]; a1 = mk[d0 + 1];
    v0 = c.x * a0 + p.x * (1.f - a0);
    v1 = c.y * a1 + p.y * (1.f - a1);
    split2(v0, v1, h, l);
    reinterpret_cast<uint32_t*>(g_xkh)[idx] = h;
    reinterpret_cast<uint32_t*>(g_xkl)[idx] = l;

    a0 = mr[d0]; a1 = mr[d0 + 1];
    v0 = c.x * a0 + p.x * (1.f - a0);
    v1 = c.y * a1 + p.y * (1.f - a1);
    split2(v0, v1, h, l);
    reinterpret_cast<uint32_t*>(g_xrh)[idx] = h;
    reinterpret_cast<uint32_t*>(g_xrl)[idx] = l;
}

// ---------------- WKV scan, writes ry = r*out as bf16 hi/lo ------------------
__global__ void __launch_bounds__(256)
wkv_kernel(const float* __restrict__ td, const float* __restrict__ tf,
           const float* __restrict__ k, const float* __restrict__ v,
           const float* __restrict__ r)
{
    int d = blockIdx.x * 256 + threadIdx.x;
    if (d >= Dn) return;
    float w = -expf(td[d]);
    float u = tf[d];
    float aa = 0.f, bb = 0.f, pp = -1e30f;
    float kt = k[d], vt = v[d];
    for (int t = 0; t < Tn; t++) {
        float kn = 0.f, vn = 0.f;
        if (t + 1 < Tn) { kn = k[(t + 1) * Dn + d]; vn = v[(t + 1) * Dn + d]; }
        float ww = u + kt;
        float qq = fmaxf(pp, ww);
        float e1 = __expf(pp - qq), e2 = __expf(ww - qq);
        float out = fmaf(e1, aa, e2 * vt) / fmaf(e1, bb, e2);
        float ww2 = pp + w;
        float qq2 = fmaxf(ww2, kt);
        e1 = __expf(ww2 - qq2); e2 = __expf(kt - qq2);
        aa = fmaf(e1, aa, e2 * vt);
        bb = fmaf(e1, bb, e2);
        pp = qq2;
        float val = r[t * Dn + d] * out;
        __nv_bfloat16 h = __float2bfloat16_rn(val);
        float rem = val - __bfloat162float(h);
        g_ryh[t * Dn + d] = h;
        g_ryl[t * Dn + d] = __float2bfloat16_rn(rem);
        kt = kn; vt = vn;
    }
}

// ---------------- bf16-split mma GEMM with cp.async pipeline -----------------
// C[M,N] = epi(A[M,K] @ B[K,N]) using A ~= Ah+Al, B ~= Bh+Bl (bf16 hi/lo).
// EPI: 0 store fp32, 1 acc+X1, 2 relu(acc)^2 -> bf16 hi/lo (Oh/Ol),
//      3 sigmoid, 4 X1 + X2*acc.  CGUARD: guard C col < N.
#define SA_H 0u
#define SA_L 10240u
#define SB_H 20480u
#define SB_L 29184u
#define STAGE_B 38144u
#define GEMM_SMEM (3 * 38144)

template<int EPI, bool CGUARD>
__global__ void __launch_bounds__(256, 1)
bgemm_kernel(const __nv_bfloat16* __restrict__ Ah, const __nv_bfloat16* __restrict__ Al,
             const __nv_bfloat16* __restrict__ Bh, const __nv_bfloat16* __restrict__ Bl,
             float* __restrict__ C, int M, int N, int K, int ldb,
             const float* __restrict__ X1, const float* __restrict__ X2,
             __nv_bfloat16* __restrict__ Oh, __nv_bfloat16* __restrict__ Ol)
{
    extern __shared__ __align__(128) char dsm[];
    const int tid  = threadIdx.x;
    const int lane = tid & 31;
    const int wid  = tid >> 5;
    const int wm   = wid >> 2;
    const int wn   = wid & 3;
    const int bm   = blockIdx.y * 128;
    const int bn   = blockIdx.x * 128;

    const uint32_t sbase = smem_u32(dsm);

    // cp.async thread mapping
    const int ar  = tid >> 1, asg = tid & 1;     // A: 128 rows, 2 thr/row
    const int br  = tid >> 3, bsg = tid & 7;     // B: 32 rows,  8 thr/row
    const __nv_bfloat16* Ah0 = Ah + (size_t)(bm + ar) * K + asg * 16;
    const __nv_bfloat16* Al0 = Al + (size_t)(bm + ar) * K + asg * 16;
    const __nv_bfloat16* Bh0 = Bh + (size_t)br * ldb + bn + bsg * 16;
    const __nv_bfloat16* Bl0 = Bl + (size_t)br * ldb + bn + bsg * 16;
    const uint32_t adst = (uint32_t)(ar * 80 + asg * 32);
    const uint32_t bdst = (uint32_t)(br * 272 + bsg * 32);

    const int nch = K >> 5;

    // ldmatrix per-thread offsets
    const uint32_t a_off = (uint32_t)(((lane & 15) * 40 + ((lane >> 4) << 3)) * 2);
    const uint32_t b_off = (uint32_t)(((lane & 15) * 136 + ((lane >> 4) << 3)) * 2);

    float acc[4][4][4];
    #pragma unroll
    for (int i = 0; i < 4; i++)
        #pragma unroll
        for (int j = 0; j < 4; j++)
            #pragma unroll
            for (int q = 0; q < 4; q++) acc[i][j][q] = 0.f;

    // stage issue
    auto issue = [&](int kc) {
        uint32_t st = sbase + (uint32_t)(kc % 3) * STAGE_B;
        const __nv_bfloat16* ah = Ah0 + kc * 32;
        const __nv_bfloat16* al = Al0 + kc * 32;
        cpa16(st + SA_H + adst,      ah);
        cpa16(st + SA_H + adst + 16, ah + 8);
        cpa16(st + SA_L + adst,      al);
        cpa16(st + SA_L + adst + 16, al + 8);
        const __nv_bfloat16* bh = Bh0 + (size_t)kc * 32 * ldb;
        const __nv_bfloat16* bl = Bl0 + (size_t)kc * 32 * ldb;
        cpa16(st + SB_H + bdst,      bh);
        cpa16(st + SB_H + bdst + 16, bh + 8);
        cpa16(st + SB_L + bdst,      bl);
        cpa16(st + SB_L + bdst + 16, bl + 8);
    };

    issue(0); CP_COMMIT();
    if (nch > 1) issue(1);
    CP_COMMIT();

    for (int kc = 0; kc < nch; kc++) {
        CP_WAIT1();
        __syncthreads();
        if (kc + 2 < nch) issue(kc + 2);
        CP_COMMIT();

        const uint32_t st = sbase + (uint32_t)(kc % 3) * STAGE_B;
        #pragma unroll
        for (int ks = 0; ks < 2; ks++) {
            uint32_t bh[4][2], bl[4][2];
            #pragma unroll
            for (int p = 0; p < 2; p++) {
                uint32_t boff = (uint32_t)((ks * 16 * 136 + wn * 32 + p * 16) * 2) + b_off;
                LDSM_X4T(st + SB_H + boff, bh[2*p][0], bh[2*p][1], bh[2*p+1][0], bh[2*p+1][1]);
                LDSM_X4T(st + SB_L + boff, bl[2*p][0], bl[2*p][1], bl[2*p+1][0], bl[2*p+1][1]);
            }
            #pragma unroll
            for (int i = 0; i < 4; i++) {
                uint32_t ah[4], al[4];
                uint32_t aoff = (uint32_t)((((wm * 64 + i * 16) * 40) + ks * 16) * 2) + a_off;
                LDSM_X4(st + SA_H + aoff, ah[0], ah[1], ah[2], ah[3]);
                LDSM_X4(st + SA_L + aoff, al[0], al[1], al[2], al[3]);
                #pragma unroll
                for (int j = 0; j < 4; j++) {
                    mma_bf16(acc[i][j], ah, bh[j][0], bh[j][1]);
                    mma_bf16(acc[i][j], al, bh[j][0], bh[j][1]);
                    mma_bf16(acc[i][j], ah, bl[j][0], bl[j][1]);
                }
            }
        }
    }

    // ---- epilogue ----
    #pragma unroll
    for (int i = 0; i < 4; i++) {
        #pragma unroll
        for (int j = 0; j < 4; j++) {
            int row = bm + wm * 64 + i * 16 + (lane >> 2);
            int col = bn + wn * 32 + j * 8 + ((lane & 3) << 1);
            #pragma unroll
            for (int h = 0; h < 2; h++) {
                int rr = row + h * 8;
                float v0 = acc[i][j][2 * h + 0];
                float v1 = acc[i][j][2 * h + 1];
                if (EPI == 2) {
                    float p0 = fmaxf(v0, 0.f), p1 = fmaxf(v1, 0.f);
                    v0 = p0 * p0; v1 = p1 * p1;
                    uint32_t hh, ll;
                    split2(v0, v1, hh, ll);
                    size_t off = ((size_t)rr * N + col) >> 1;
                    reinterpret_cast<uint32_t*>(Oh)[off] = hh;
                    reinterpret_cast<uint32_t*>(Ol)[off] = ll;
                } else {
                    float* crow = C + (size_t)rr * N;
                    if (EPI == 1) {
                        const float* x1 = X1 + (size_t)rr * N;
                        v0 += x1[col]; v1 += x1[col + 1];
                    } else if (EPI == 3) {
                        v0 = 1.f / (1.f + expf(-v0));
                        v1 = 1.f / (1.f + expf(-v1));
                    } else if (EPI == 4) {
                        const float* x1 = X1 + (size_t)rr * N;
                        const float* x2 = X2 + (size_t)rr * N;
                        v0 = x1[col]     + x2[col]     * v0;
                        v1 = x1[col + 1] + x2[col + 1] * v1;
                    }
                    if (CGUARD) {
                        if (col < N)     crow[col]     = v0;
                        if (col + 1 < N) crow[col + 1] = v1;
                    } else {
                        *reinterpret_cast<float2*>(crow + col) = make_float2(v0, v1);
                    }
                }
            }
        }
    }
}

// ---------------- host orchestration ----------------
extern "C" void kernel_launch(void* const* d_in, const int* in_sizes, int n_in,
                              void* d_out, int out_size)
{
    const int*   tokens   = (const int*)  d_in[0];
    const float* emb      = (const float*)d_in[1];
    const float* tm_decay = (const float*)d_in[2];
    const float* tm_first = (const float*)d_in[3];
    const float* tm_mix_k = (const float*)d_in[4];
    const float* tm_mix_v = (const float*)d_in[5];
    const float* tm_mix_r = (const float*)d_in[6];
    const float* tm_Wk    = (const float*)d_in[7];
    const float* tm_Wv    = (const float*)d_in[8];
    const float* tm_Wr    = (const float*)d_in[9];
    const float* tm_Wo    = (const float*)d_in[10];
    const float* cm_mix_k = (const float*)d_in[11];
    const float* cm_mix_r = (const float*)d_in[12];
    const float* cm_Wk    = (const float*)d_in[13];
    const float* cm_Wv    = (const float*)d_in[14];
    const float* cm_Wr    = (const float*)d_in[15];
    const float* ln0_w    = (const float*)d_in[16];
    const float* ln0_b    = (const float*)d_in[17];
    const float* ln1_w    = (const float*)d_in[18];
    const float* ln1_b    = (const float*)d_in[19];
    const float* ln2_w    = (const float*)d_in[20];
    const float* ln2_b    = (const float*)d_in[21];
    const float* lnout_w  = (const float*)d_in[22];
    const float* lnout_b  = (const float*)d_in[23];
    const float* head_W   = (const float*)d_in[24];
    float* out = (float*)d_out;

    float *x_, *xn_, *k_, *v_, *r_, *rr_;
    __nv_bfloat16 *wh_, *wl_;
    __nv_bfloat16 *xkh_, *xkl_, *xvh_, *xvl_, *xrh_, *xrl_;
    __nv_bfloat16 *ryh_, *ryl_, *xnh_, *xnl_, *kkh_, *kkl_;
    cudaGetSymbolAddress((void**)&x_,  g_x);
    cudaGetSymbolAddress((void**)&xn_, g_xn);
    cudaGetSymbolAddress((void**)&k_,  g_k);
    cudaGetSymbolAddress((void**)&v_,  g_v);
    cudaGetSymbolAddress((void**)&r_,  g_r);
    cudaGetSymbolAddress((void**)&rr_, g_rr);
    cudaGetSymbolAddress((void**)&wh_, g_wh);
    cudaGetSymbolAddress((void**)&wl_, g_wl);
    cudaGetSymbolAddress((void**)&xkh_, g_xkh);
    cudaGetSymbolAddress((void**)&xkl_, g_xkl);
    cudaGetSymbolAddress((void**)&xvh_, g_xvh);
    cudaGetSymbolAddress((void**)&xvl_, g_xvl);
    cudaGetSymbolAddress((void**)&xrh_, g_xrh);
    cudaGetSymbolAddress((void**)&xrl_, g_xrl);
    cudaGetSymbolAddress((void**)&ryh_, g_ryh);
    cudaGetSymbolAddress((void**)&ryl_, g_ryl);
    cudaGetSymbolAddress((void**)&xnh_, g_xnh);
    cudaGetSymbolAddress((void**)&xnl_, g_xnl);
    cudaGetSymbolAddress((void**)&kkh_, g_kkh);
    cudaGetSymbolAddress((void**)&kkl_, g_kkl);

    cudaFuncSetAttribute(bgemm_kernel<0,false>, cudaFuncAttributeMaxDynamicSharedMemorySize, GEMM_SMEM);
    cudaFuncSetAttribute(bgemm_kernel<1,false>, cudaFuncAttributeMaxDynamicSharedMemorySize, GEMM_SMEM);
    cudaFuncSetAttribute(bgemm_kernel<2,false>, cudaFuncAttributeMaxDynamicSharedMemorySize, GEMM_SMEM);
    cudaFuncSetAttribute(bgemm_kernel<3,false>, cudaFuncAttributeMaxDynamicSharedMemorySize, GEMM_SMEM);
    cudaFuncSetAttribute(bgemm_kernel<4,false>, cudaFuncAttributeMaxDynamicSharedMemorySize, GEMM_SMEM);
    cudaFuncSetAttribute(bgemm_kernel<0,true>,  cudaFuncAttributeMaxDynamicSharedMemorySize, GEMM_SMEM);

    // ---- split all weights into bf16 hi/lo pools ----
    wsplit_kernel<<<dim3(2, Ln * Dn), 256>>>(tm_Wk, wh_ + OFF_TWK, wl_ + OFF_TWK, Dn, Dn);
    wsplit_kernel<<<dim3(2, Ln * Dn), 256>>>(tm_Wv, wh_ + OFF_TWV, wl_ + OFF_TWV, Dn, Dn);
    wsplit_kernel<<<dim3(2, Ln * Dn), 256>>>(tm_Wr, wh_ + OFF_TWR, wl_ + OFF_TWR, Dn, Dn);
    wsplit_kernel<<<dim3(2, Ln * Dn), 256>>>(tm_Wo, wh_ + OFF_TWO, wl_ + OFF_TWO, Dn, Dn);
    wsplit_kernel<<<dim3(8, Ln * Dn), 256>>>(cm_Wk, wh_ + OFF_CWK, wl_ + OFF_CWK, Hn, Hn);
    wsplit_kernel<<<dim3(2, Ln * Hn), 256>>>(cm_Wv, wh_ + OFF_CWV, wl_ + OFF_CWV, Dn, Dn);
    wsplit_kernel<<<dim3(2, Ln * Dn), 256>>>(cm_Wr, wh_ + OFF_CWR, wl_ + OFF_CWR, Dn, Dn);
    wsplit_kernel<<<dim3(99, Dn), 256>>>(head_W, wh_ + OFF_HEAD, wl_ + OFF_HEAD, Vn, VP);

    const int pw = (Tn * Dn / 2 + 255) / 256;
    dim3 gDD(Dn / 128, Tn / 128);
    dim3 gDH(Hn / 128, Tn / 128);
    dim3 gHV(VP / 128, Tn / 128);

    ln_kernel<<<Tn, 256>>>(emb, tokens, ln0_w, ln0_b, x_);

    for (int l = 0; l < Ln; l++) {
        const __nv_bfloat16* Wkh = wh_ + OFF_TWK + (size_t)l * Dn * Dn;
        const __nv_bfloat16* Wkl = wl_ + OFF_TWK + (size_t)l * Dn * Dn;
        const __nv_bfloat16* Wvh = wh_ + OFF_TWV + (size_t)l * Dn * Dn;
        const __nv_bfloat16* Wvl = wl_ + OFF_TWV + (size_t)l * Dn * Dn;
        const __nv_bfloat16* Wrh = wh_ + OFF_TWR + (size_t)l * Dn * Dn;
        const __nv_bfloat16* Wrl = wl_ + OFF_TWR + (size_t)l * Dn * Dn;
        const __nv_bfloat16* Woh = wh_ + OFF_TWO + (size_t)l * Dn * Dn;
        const __nv_bfloat16* Wol = wl_ + OFF_TWO + (size_t)l * Dn * Dn;
        const __nv_bfloat16* CWkh = wh_ + OFF_CWK + (size_t)l * Dn * Hn;
        const __nv_bfloat16* CWkl = wl_ + OFF_CWK + (size_t)l * Dn * Hn;
        const __nv_bfloat16* CWvh = wh_ + OFF_CWV + (size_t)l * Hn * Dn;
        const __nv_bfloat16* CWvl = wl_ + OFF_CWV + (size_t)l * Hn * Dn;
        const __nv_bfloat16* CWrh = wh_ + OFF_CWR + (size_t)l * Dn * Dn;
        const __nv_bfloat16* CWrl = wl_ + OFF_CWR + (size_t)l * Dn * Dn;

        ln_kernel<<<Tn, 256>>>(x_, nullptr, ln1_w + l * Dn, ln1_b + l * Dn, x_);

        mix3_split_kernel<<<pw, 256>>>(x_, tm_mix_k + l * Dn, tm_mix_v + l * Dn,
                                       tm_mix_r + l * Dn);

        bgemm_kernel<0,false><<<gDD, 256, GEMM_SMEM>>>(xkh_, xkl_, Wkh, Wkl, k_,  Tn, Dn, Dn, Dn, nullptr, nullptr, nullptr, nullptr);
        bgemm_kernel<0,false><<<gDD, 256, GEMM_SMEM>>>(xvh_, xvl_, Wvh, Wvl, v_,  Tn, Dn, Dn, Dn, nullptr, nullptr, nullptr, nullptr);
        bgemm_kernel<3,false><<<gDD, 256, GEMM_SMEM>>>(xrh_, xrl_, Wrh, Wrl, r_,  Tn, Dn, Dn, Dn, nullptr, nullptr, nullptr, nullptr);

        wkv_kernel<<<Dn / 256, 256>>>(tm_decay + l * Dn, tm_first + l * Dn, k_, v_, r_);

        bgemm_kernel<1,false><<<gDD, 256, GEMM_SMEM>>>(ryh_, ryl_, Woh, Wol, x_, Tn, Dn, Dn, Dn, x_, nullptr, nullptr, nullptr);

        ln_kernel<<<Tn, 256>>>(x_, nullptr, ln2_w + l * Dn, ln2_b + l * Dn, xn_);
        mix2_split_kernel<<<pw, 256>>>(xn_, cm_mix_k + l * Dn, cm_mix_r + l * Dn);

        bgemm_kernel<2,false><<<gDH, 256, GEMM_SMEM>>>(xkh_, xkl_, CWkh, CWkl, nullptr, Tn, Hn, Dn, Hn, nullptr, nullptr, kkh_, kkl_);
        bgemm_kernel<3,false><<<gDD, 256, GEMM_SMEM>>>(xrh_, xrl_, CWrh, CWrl, rr_, Tn, Dn, Dn, Dn, nullptr, nullptr, nullptr, nullptr);
        bgemm_kernel<4,false><<<gDD, 256, GEMM_SMEM>>>(kkh_, kkl_, CWvh, CWvl, x_, Tn, Dn, Hn, Dn, x_, rr_, nullptr, nullptr);
    }

    ln_split_kernel<<<Tn, 256>>>(x_, lnout_w, lnout_b, xnh_, xnl_);
    bgemm_kernel<0,true><<<gHV, 256, GEMM_SMEM>>>(xnh_, xnl_, wh_ + OFF_HEAD, wl_ + OFF_HEAD,
                                                  out, Tn, Vn, Dn, VP, nullptr, nullptr, nullptr, nullptr);
}